// round 1
// baseline (speedup 1.0000x reference)
#include <cuda_runtime.h>

// WindowAttention fused kernel, fp32 baseline.
// Windows: 16*3136 = 50176, each [16 tokens, 96 ch], H=8 heads, D=12.
// Persistent CTAs; all weights resident in SMEM; 2 windows per iteration.

#define NWIN      50176
#define WPB       2          // windows per block-iteration
#define NGROUPS   (NWIN / WPB)   // 25088
#define L_DIM     3136
#define SCALE     0.28867513459481287f  // 12^-0.5

// SMEM layout (floats)
#define OFF_WS   0          // qkv_kernel [96][288]
#define OFF_BQ   27648      // qkv_bias [288]
#define OFF_WP   27936      // proj_kernel [96][96]
#define OFF_BP   37152      // proj_bias [96]
#define OFF_RB   37248      // rel_bias [8][16][16]
#define OFF_XS   39296      // x tile [32][100]  (aliased as attn-out later)
#define OFF_QS   42496      // qkv tile [32][292]
#define SMEM_FLOATS 51840
#define SMEM_BYTES  (SMEM_FLOATS * 4)   // 207,360 B

__global__ __launch_bounds__(256, 1)
void win_attn_kernel(const float* __restrict__ x,
                     const float* __restrict__ mask,
                     const float* __restrict__ qkv_w,
                     const float* __restrict__ qkv_b,
                     const float* __restrict__ proj_w,
                     const float* __restrict__ proj_b,
                     const float* __restrict__ bias_table,
                     float* __restrict__ out)
{
    extern __shared__ float sm[];
    float* WS = sm + OFF_WS;
    float* BQ = sm + OFF_BQ;
    float* WP = sm + OFF_WP;
    float* BP = sm + OFF_BP;
    float* RB = sm + OFF_RB;
    float* XS = sm + OFF_XS;   // [32][100]
    float* QS = sm + OFF_QS;   // [32][292]
    float* OS = XS;            // attn output aliases XS (x dead by then)

    const int t = threadIdx.x;

    // ---- One-time weight staging ----
    for (int i = t; i < 27648; i += 256) WS[i] = qkv_w[i];
    for (int i = t; i < 288;   i += 256) BQ[i] = qkv_b[i];
    for (int i = t; i < 9216;  i += 256) WP[i] = proj_w[i];
    if (t < 96) BP[t] = proj_b[t];
    // rel_bias[h][i][j] = bias_table[ ((i%4-j%4)+3)*7 + ((i/4-j/4)+3) ][h]
    for (int i = t; i < 2048; i += 256) {
        int h  = i >> 8;
        int ij = i & 255;
        int ii = ij >> 4, jj = ij & 15;
        int d0 = (ii & 3)  - (jj & 3)  + 3;
        int d1 = (ii >> 2) - (jj >> 2) + 3;
        RB[i] = bias_table[(d0 * 7 + d1) * 8 + h];
    }
    __syncthreads();

    // Thread roles
    const int rg = t >> 5;          // 0..7  row group (GEMM stages)
    const int cg = t & 31;          // 0..31 column lane
    const int w  = t >> 7;          // 0..1  window (attn stage)
    const int h  = (t >> 4) & 7;    // 0..7  head
    const int ti = t & 15;          // 0..15 query row

    for (int g = blockIdx.x; g < NGROUPS; g += gridDim.x) {
        // ---- Stage A: load x (2 windows = 3072 contiguous floats) ----
        {
            const float4* xg = (const float4*)(x + (size_t)g * 3072);
            #pragma unroll
            for (int p = 0; p < 3; p++) {
                int p4   = t + p * 256;          // 0..767
                int row  = p4 / 24;              // 24 float4 per 96-col row
                int col4 = p4 % 24;
                ((float4*)&XS[row * 100])[col4] = xg[p4];
            }
        }
        __syncthreads();

        // ---- Stage B: QKV GEMM  [32,96] @ [96,288] + bias -> QS ----
        {
            float acc[4][9];
            #pragma unroll
            for (int j = 0; j < 9; j++) {
                float b = BQ[cg + 32 * j];
                acc[0][j] = b; acc[1][j] = b; acc[2][j] = b; acc[3][j] = b;
            }
            const float* xr = &XS[(rg * 4) * 100];
            #pragma unroll 4
            for (int k = 0; k < 96; k++) {
                float a0 = xr[k], a1 = xr[100 + k], a2 = xr[200 + k], a3 = xr[300 + k];
                const float* wk = &WS[k * 288 + cg];
                #pragma unroll
                for (int j = 0; j < 9; j++) {
                    float wv = wk[32 * j];
                    acc[0][j] += a0 * wv; acc[1][j] += a1 * wv;
                    acc[2][j] += a2 * wv; acc[3][j] += a3 * wv;
                }
            }
            #pragma unroll
            for (int ri = 0; ri < 4; ri++)
                #pragma unroll
                for (int j = 0; j < 9; j++)
                    QS[(rg * 4 + ri) * 292 + cg + 32 * j] = acc[ri][j];
        }
        __syncthreads();

        // ---- Stage C: attention. thread = (w, h, ti) ----
        {
            const int   l    = (g * WPB + w) % L_DIM;
            const float* qrow = &QS[(w * 16 + ti) * 292 + h * 12];
            float qreg[12];
            #pragma unroll
            for (int d = 0; d < 12; d++) qreg[d] = qrow[d] * SCALE;

            const float* rbrow = &RB[h * 256 + ti * 16];
            const float* mrow  = mask + (size_t)l * 256 + ti * 16;

            float sc[16];
            #pragma unroll
            for (int j = 0; j < 16; j++) {
                const float4* kr = (const float4*)&QS[(w * 16 + j) * 292 + 96 + h * 12];
                float4 k0 = kr[0], k1 = kr[1], k2 = kr[2];
                float s = rbrow[j] + mrow[j];
                s += qreg[0]*k0.x + qreg[1]*k0.y + qreg[2] *k0.z + qreg[3] *k0.w
                   + qreg[4]*k1.x + qreg[5]*k1.y + qreg[6] *k1.z + qreg[7] *k1.w
                   + qreg[8]*k2.x + qreg[9]*k2.y + qreg[10]*k2.z + qreg[11]*k2.w;
                sc[j] = s;
            }
            float m = sc[0];
            #pragma unroll
            for (int j = 1; j < 16; j++) m = fmaxf(m, sc[j]);
            float sum = 0.f;
            #pragma unroll
            for (int j = 0; j < 16; j++) { sc[j] = __expf(sc[j] - m); sum += sc[j]; }
            float inv = __fdividef(1.f, sum);

            float o[12];
            #pragma unroll
            for (int d = 0; d < 12; d++) o[d] = 0.f;
            #pragma unroll
            for (int j = 0; j < 16; j++) {
                const float4* vr = (const float4*)&QS[(w * 16 + j) * 292 + 192 + h * 12];
                float4 v0 = vr[0], v1 = vr[1], v2 = vr[2];
                float p = sc[j];
                o[0] += p*v0.x; o[1] += p*v0.y; o[2]  += p*v0.z; o[3]  += p*v0.w;
                o[4] += p*v1.x; o[5] += p*v1.y; o[6]  += p*v1.z; o[7]  += p*v1.w;
                o[8] += p*v2.x; o[9] += p*v2.y; o[10] += p*v2.z; o[11] += p*v2.w;
            }
            float* orow = &OS[(w * 16 + ti) * 100 + h * 12];
            #pragma unroll
            for (int d = 0; d < 12; d++) orow[d] = o[d] * inv;
        }
        __syncthreads();

        // ---- Stage D: proj  [32,96] @ [96,96] + bias -> global ----
        {
            float acc[4][3];
            #pragma unroll
            for (int j = 0; j < 3; j++) {
                float b = BP[cg + 32 * j];
                acc[0][j] = b; acc[1][j] = b; acc[2][j] = b; acc[3][j] = b;
            }
            const float* orow = &OS[(rg * 4) * 100];
            #pragma unroll 8
            for (int k = 0; k < 96; k++) {
                float a0 = orow[k], a1 = orow[100 + k], a2 = orow[200 + k], a3 = orow[300 + k];
                const float* wk = &WP[k * 96 + cg];
                #pragma unroll
                for (int j = 0; j < 3; j++) {
                    float wv = wk[32 * j];
                    acc[0][j] += a0 * wv; acc[1][j] += a1 * wv;
                    acc[2][j] += a2 * wv; acc[3][j] += a3 * wv;
                }
            }
            float* og = out + (size_t)g * 3072;
            #pragma unroll
            for (int ri = 0; ri < 4; ri++)
                #pragma unroll
                for (int j = 0; j < 3; j++)
                    og[(rg * 4 + ri) * 96 + cg + 32 * j] = acc[ri][j];
        }
        __syncthreads();  // protect XS/OS reuse before next iteration
    }
}

extern "C" void kernel_launch(void* const* d_in, const int* in_sizes, int n_in,
                              void* d_out, int out_size)
{
    const float* x          = (const float*)d_in[0];
    const float* mask       = (const float*)d_in[1];
    const float* qkv_w      = (const float*)d_in[2];
    const float* qkv_b      = (const float*)d_in[3];
    const float* proj_w     = (const float*)d_in[4];
    const float* proj_b     = (const float*)d_in[5];
    const float* bias_table = (const float*)d_in[6];
    float* out = (float*)d_out;

    int sms = 148;
    cudaDeviceGetAttribute(&sms, cudaDevAttrMultiProcessorCount, 0);
    cudaFuncSetAttribute(win_attn_kernel,
                         cudaFuncAttributeMaxDynamicSharedMemorySize, SMEM_BYTES);

    win_attn_kernel<<<sms, 256, SMEM_BYTES>>>(x, mask, qkv_w, qkv_b,
                                              proj_w, proj_b, bias_table, out);
}

// round 2
// speedup vs baseline: 1.1350x; 1.1350x over previous
#include <cuda_runtime.h>

// WindowAttention fused kernel, fp32 with packed f32x2 FMA (FFMA2).
// Windows: 50176 of [16 tok, 96 ch], H=8, D=12. Persistent CTAs,
// weights SMEM-resident, 3 windows per iteration (tail-guarded).

#define NWIN      50176
#define WPB       3
#define NGROUPS   ((NWIN + WPB - 1) / WPB)   // 16726
#define L_DIM     3136
#define SCALE     0.28867513459481287f       // 12^-0.5

// SMEM layout (floats)
#define OFF_WS    0          // qkv_kernel [96][288]
#define OFF_BQ    27648      // qkv_bias [288]
#define OFF_WP    27936      // proj_kernel [96][96]
#define OFF_BP    37152      // proj_bias [96]
#define OFF_XSP   37248      // x pairs [96][25 float2] = 4800 floats (aliased as OSP)
#define OFF_QS    42048      // qkv tile [48][292] = 14016 floats
#define SMEM_FLOATS 56064
#define SMEM_BYTES  (SMEM_FLOATS * 4)        // 224,256 B

#define XSP_STRIDE 50        // floats per k-row of pair storage (25 float2)

typedef unsigned long long u64;

__device__ __forceinline__ u64 pack2(float lo, float hi) {
    u64 r; asm("mov.b64 %0, {%1, %2};" : "=l"(r) : "f"(lo), "f"(hi)); return r;
}
__device__ __forceinline__ void ffma2(u64& d, u64 a, u64 b) {
    asm("fma.rn.f32x2 %0, %1, %2, %3;" : "=l"(d) : "l"(a), "l"(b), "l"(d));
}
__device__ __forceinline__ float2 unpack2(u64 v) {
    float2 r; asm("mov.b64 {%0, %1}, %2;" : "=f"(r.x), "=f"(r.y) : "l"(v)); return r;
}

__global__ __launch_bounds__(256, 1)
void win_attn_kernel(const float* __restrict__ x,
                     const float* __restrict__ mask,
                     const float* __restrict__ qkv_w,
                     const float* __restrict__ qkv_b,
                     const float* __restrict__ proj_w,
                     const float* __restrict__ proj_b,
                     const float* __restrict__ bias_table,
                     float* __restrict__ out)
{
    extern __shared__ float sm[];
    float* WS   = sm + OFF_WS;
    float* BQ   = sm + OFF_BQ;
    float* WP   = sm + OFF_WP;
    float* BP   = sm + OFF_BP;
    float* XSPf = sm + OFF_XSP;   // pair layout: [k][pair] float2
    float* QS   = sm + OFF_QS;    // [48][292]
    float* OSPf = XSPf;           // attn-out pair layout aliases XSP

    const int t = threadIdx.x;

    // ---- One-time weight staging ----
    for (int i = t; i < 27648; i += 256) WS[i] = qkv_w[i];
    for (int i = t; i < 288;   i += 256) BQ[i] = qkv_b[i];
    for (int i = t; i < 9216;  i += 256) WP[i] = proj_w[i];
    if (t < 96) BP[t] = proj_b[t];
    __syncthreads();

    const int rg = t >> 5;       // warp id 0..7: owns rows 6rg..6rg+5 (pairs 3rg..3rg+2)
    const int cg = t & 31;       // lane: column within each 32-col group

    for (int g = blockIdx.x; g < NGROUPS; g += gridDim.x) {
        const int nvalid = min(WPB, NWIN - g * WPB);   // windows in this group
        const int nrow_v = nvalid * 16;

        // ---- Stage A: load x -> transposed pair layout XSP[k][pair] ----
        {
            const float4* xg = (const float4*)(x + (size_t)g * (WPB * 1536));
            const int nf4 = nvalid * 384;              // float4 count
            for (int i = t; i < nf4; i += 256) {
                float4 v = xg[i];
                int row  = i / 24;                     // 0..47
                int col  = (i % 24) * 4;               // 0..92
                int base = (row >> 1) * 2 + (row & 1); // pair slot + half
                XSPf[(col + 0) * XSP_STRIDE + base] = v.x;
                XSPf[(col + 1) * XSP_STRIDE + base] = v.y;
                XSPf[(col + 2) * XSP_STRIDE + base] = v.z;
                XSPf[(col + 3) * XSP_STRIDE + base] = v.w;
            }
        }
        __syncthreads();

        // ---- Stage B: QKV GEMM [48,96]@[96,288]+bias -> QS, packed rows ----
        {
            u64 acc[3][9];
            #pragma unroll
            for (int j = 0; j < 9; j++) {
                float b = BQ[cg + 32 * j];
                u64 bb = pack2(b, b);
                acc[0][j] = bb; acc[1][j] = bb; acc[2][j] = bb;
            }
            const int pbase = 3 * rg;
            #pragma unroll 4
            for (int k = 0; k < 96; k++) {
                const float* xk = &XSPf[k * XSP_STRIDE + pbase * 2];
                u64 x0 = *(const u64*)(xk + 0);
                u64 x1 = *(const u64*)(xk + 2);
                u64 x2 = *(const u64*)(xk + 4);
                const float* wk = &WS[k * 288 + cg];
                #pragma unroll
                for (int j = 0; j < 9; j++) {
                    float w = wk[32 * j];
                    u64 wp = pack2(w, w);
                    ffma2(acc[0][j], x0, wp);
                    ffma2(acc[1][j], x1, wp);
                    ffma2(acc[2][j], x2, wp);
                }
            }
            #pragma unroll
            for (int p = 0; p < 3; p++) {
                int r0 = 6 * rg + 2 * p;
                #pragma unroll
                for (int j = 0; j < 9; j++) {
                    float2 v = unpack2(acc[p][j]);
                    QS[(r0 + 0) * 292 + 32 * j + cg] = v.x;
                    QS[(r0 + 1) * 292 + 32 * j + cg] = v.y;
                }
            }
        }
        __syncthreads();

        // ---- Stage C: attention. slot = (w, h, ti), 384 slots / 256 thr ----
        for (int s = t; s < WPB * 128; s += 256) {
            const int w  = s >> 7;
            const int hh = (s >> 4) & 7;
            const int ti = s & 15;
            const int wi = g * WPB + w;
            if (wi >= NWIN) continue;

            const float* qrow = &QS[(w * 16 + ti) * 292 + hh * 12];
            float qreg[12];
            #pragma unroll
            for (int d = 0; d < 12; d++) qreg[d] = qrow[d] * SCALE;

            const float* mrow = mask + (size_t)(wi % L_DIM) * 256 + ti * 16;
            const int d0b = (ti & 3) + 3, d1b = (ti >> 2) + 3;

            float sc[16];
            #pragma unroll
            for (int j = 0; j < 16; j++) {
                const float4* kr = (const float4*)&QS[(w * 16 + j) * 292 + 96 + hh * 12];
                float4 k0 = kr[0], k1 = kr[1], k2 = kr[2];
                int d0 = d0b - (j & 3), d1 = d1b - (j >> 2);
                float s2 = bias_table[(d0 * 7 + d1) * 8 + hh] + mrow[j];
                s2 += qreg[0]*k0.x + qreg[1]*k0.y + qreg[2] *k0.z + qreg[3] *k0.w
                    + qreg[4]*k1.x + qreg[5]*k1.y + qreg[6] *k1.z + qreg[7] *k1.w
                    + qreg[8]*k2.x + qreg[9]*k2.y + qreg[10]*k2.z + qreg[11]*k2.w;
                sc[j] = s2;
            }
            float m = sc[0];
            #pragma unroll
            for (int j = 1; j < 16; j++) m = fmaxf(m, sc[j]);
            float sum = 0.f;
            #pragma unroll
            for (int j = 0; j < 16; j++) { sc[j] = __expf(sc[j] - m); sum += sc[j]; }
            float inv = __fdividef(1.f, sum);

            float o[12];
            #pragma unroll
            for (int d = 0; d < 12; d++) o[d] = 0.f;
            #pragma unroll
            for (int j = 0; j < 16; j++) {
                const float4* vr = (const float4*)&QS[(w * 16 + j) * 292 + 192 + hh * 12];
                float4 v0 = vr[0], v1 = vr[1], v2 = vr[2];
                float p = sc[j];
                o[0] += p*v0.x; o[1] += p*v0.y; o[2]  += p*v0.z; o[3]  += p*v0.w;
                o[4] += p*v1.x; o[5] += p*v1.y; o[6]  += p*v1.z; o[7]  += p*v1.w;
                o[8] += p*v2.x; o[9] += p*v2.y; o[10] += p*v2.z; o[11] += p*v2.w;
            }
            const int rowg = w * 16 + ti;
            const int base = (rowg >> 1) * 2 + (rowg & 1);
            #pragma unroll
            for (int d = 0; d < 12; d++)
                OSPf[(hh * 12 + d) * XSP_STRIDE + base] = o[d] * inv;
        }
        __syncthreads();

        // ---- Stage D: proj [48,96]@[96,96]+bias -> global, packed rows ----
        {
            u64 acc[3][3];
            #pragma unroll
            for (int j = 0; j < 3; j++) {
                float b = BP[cg + 32 * j];
                u64 bb = pack2(b, b);
                acc[0][j] = bb; acc[1][j] = bb; acc[2][j] = bb;
            }
            const int pbase = 3 * rg;
            #pragma unroll 8
            for (int k = 0; k < 96; k++) {
                const float* ok = &OSPf[k * XSP_STRIDE + pbase * 2];
                u64 x0 = *(const u64*)(ok + 0);
                u64 x1 = *(const u64*)(ok + 2);
                u64 x2 = *(const u64*)(ok + 4);
                const float* wk = &WP[k * 96 + cg];
                #pragma unroll
                for (int j = 0; j < 3; j++) {
                    float w = wk[32 * j];
                    u64 wp = pack2(w, w);
                    ffma2(acc[0][j], x0, wp);
                    ffma2(acc[1][j], x1, wp);
                    ffma2(acc[2][j], x2, wp);
                }
            }
            float* og = out + (size_t)g * (WPB * 1536);
            #pragma unroll
            for (int p = 0; p < 3; p++) {
                int r0 = 6 * rg + 2 * p;
                #pragma unroll
                for (int j = 0; j < 3; j++) {
                    float2 v = unpack2(acc[p][j]);
                    if (r0 < nrow_v)     og[(r0 + 0) * 96 + 32 * j + cg] = v.x;
                    if (r0 + 1 < nrow_v) og[(r0 + 1) * 96 + 32 * j + cg] = v.y;
                }
            }
        }
        __syncthreads();   // protect XSP/OSP + QS reuse next iteration
    }
}

extern "C" void kernel_launch(void* const* d_in, const int* in_sizes, int n_in,
                              void* d_out, int out_size)
{
    const float* x          = (const float*)d_in[0];
    const float* mask       = (const float*)d_in[1];
    const float* qkv_w      = (const float*)d_in[2];
    const float* qkv_b      = (const float*)d_in[3];
    const float* proj_w     = (const float*)d_in[4];
    const float* proj_b     = (const float*)d_in[5];
    const float* bias_table = (const float*)d_in[6];
    float* out = (float*)d_out;

    int sms = 148;
    cudaDeviceGetAttribute(&sms, cudaDevAttrMultiProcessorCount, 0);
    cudaFuncSetAttribute(win_attn_kernel,
                         cudaFuncAttributeMaxDynamicSharedMemorySize, SMEM_BYTES);

    win_attn_kernel<<<sms, 256, SMEM_BYTES>>>(x, mask, qkv_w, qkv_b,
                                              proj_w, proj_b, bias_table, out);
}

// round 5
// speedup vs baseline: 2.5315x; 2.2304x over previous
#include <cuda_runtime.h>

// WindowAttention: warp-level tf32 mma.sync GEMMs + fp32 scalar attention.
// 50176 windows of [16 tok, 96 ch], H=8, D=12. Persistent CTAs, 8 warps.
// Each warp owns one window per tile; the whole pipeline is warp-local.

#define NWIN   50176
#define NTILES (NWIN / 8)      // 6272
#define L_DIM  3136
#define SCALE  0.28867513459481287f

// SMEM layout (bytes)
#define OFF_PQ   0             // QKV B-pack: 36 nc * 12 ks * 32 ln * 2 u32 = 110592 B
#define OFF_QKVS 110592        // [128][76] f  = 38912 B (per-warp 16-row slices)
#define OFF_OS   149504        // [128][100] f = 51200 B (attn out)
#define OFF_RB   200704        // rel bias [4 hp][16 j][16 ti][2 hsel] = 8192 B
#define OFF_BQ   208896        // qkv_bias 288 f
#define OFF_BP   210048        // proj_bias 96 f
#define SMEM_BYTES 210432

typedef unsigned int u32;

__device__ u32 PRJPACK[12 * 12 * 64];   // proj B-pack (tf32), global scratch

__device__ __forceinline__ u32 f2tf(float f) {
    u32 r; asm("cvt.rna.tf32.f32 %0, %1;" : "=r"(r) : "f"(f)); return r;
}
__device__ __forceinline__ void mma8(float& c0, float& c1, float& c2, float& c3,
                                     u32 a0, u32 a1, u32 a2, u32 a3,
                                     u32 b0, u32 b1) {
    asm volatile(
        "mma.sync.aligned.m16n8k8.row.col.f32.tf32.tf32.f32 "
        "{%0,%1,%2,%3}, {%4,%5,%6,%7}, {%8,%9}, {%0,%1,%2,%3};"
        : "+f"(c0), "+f"(c1), "+f"(c2), "+f"(c3)
        : "r"(a0), "r"(a1), "r"(a2), "r"(a3), "r"(b0), "r"(b1));
}

__global__ __launch_bounds__(256, 1)
void win_attn_kernel(const float* __restrict__ x,
                     const float* __restrict__ mask,
                     const float* __restrict__ qkv_w,
                     const float* __restrict__ qkv_b,
                     const float* __restrict__ proj_w,
                     const float* __restrict__ proj_b,
                     const float* __restrict__ bias_table,
                     float* __restrict__ out)
{
    extern __shared__ char smb[];
    u32*   PQ  = (u32*)(smb + OFF_PQ);
    float* QK  = (float*)(smb + OFF_QKVS);
    float* OSf = (float*)(smb + OFF_OS);
    float* RB  = (float*)(smb + OFF_RB);
    float* BQf = (float*)(smb + OFF_BQ);
    float* BPf = (float*)(smb + OFF_BP);

    const int t = threadIdx.x;

    // ---- One-time staging ----
    // QKV B fragments: pack[(nc*12+ks)*32+ln] = {W[k0][n], W[k0+4][n]} (tf32)
    for (int i = t; i < 36 * 12 * 32; i += 256) {
        int nc = i / 384, r = i % 384, ks = r / 32, lnn = r % 32;
        int k0 = ks * 8 + (lnn & 3), n = nc * 8 + (lnn >> 2);
        PQ[i * 2 + 0] = f2tf(qkv_w[k0 * 288 + n]);
        PQ[i * 2 + 1] = f2tf(qkv_w[(k0 + 4) * 288 + n]);
    }
    // proj B fragments -> global scratch (all CTAs write identical data)
    for (int i = t; i < 12 * 12 * 32; i += 256) {
        int nc = i / 384, r = i % 384, ks = r / 32, lnn = r % 32;
        int k0 = ks * 8 + (lnn & 3), n = nc * 8 + (lnn >> 2);
        PRJPACK[i * 2 + 0] = f2tf(proj_w[k0 * 96 + n]);
        PRJPACK[i * 2 + 1] = f2tf(proj_w[(k0 + 4) * 96 + n]);
    }
    // rel bias, bank-conflict-free layout [hp][j][ti][hsel]
    for (int i = t; i < 2048; i += 256) {
        int hsel = i & 1, ti = (i >> 1) & 15, j = (i >> 5) & 15, hp = i >> 9;
        int h  = 2 * hp + hsel;
        int d0 = (ti & 3)  - (j & 3)  + 3;
        int d1 = (ti >> 2) - (j >> 2) + 3;
        RB[i] = bias_table[(d0 * 7 + d1) * 8 + h];
    }
    for (int i = t; i < 288; i += 256) BQf[i] = qkv_b[i];
    if (t < 96) BPf[t] = proj_b[t];
    __syncthreads();

    const int w    = t >> 5;        // warp = window within tile
    const int ln   = t & 31;
    const int gi   = ln >> 2;       // fragment group row 0..7
    const int tg   = ln & 3;        // fragment col-in-group
    const int hsel = ln >> 4;       // attention: head-in-pair
    const int ti   = ln & 15;       // attention: query row

    for (int g = blockIdx.x; g < NTILES; g += gridDim.x) {
        // ---- A fragments of x [16,96] (tf32), held in registers ----
        u32 af[48];
        {
            const float* xw = x + (size_t)g * 12288 + (size_t)w * 1536 + gi * 96 + tg;
            #pragma unroll
            for (int ks = 0; ks < 12; ks++) {
                af[ks*4+0] = f2tf(xw[ks*8]);
                af[ks*4+1] = f2tf(xw[768 + ks*8]);
                af[ks*4+2] = f2tf(xw[ks*8 + 4]);
                af[ks*4+3] = f2tf(xw[768 + ks*8 + 4]);
            }
        }
        // ---- mask row for this lane ----
        float m[16];
        {
            const float4* mp = (const float4*)(mask +
                (size_t)((g * 8 + w) % L_DIM) * 256 + ti * 16);
            float4 m0 = mp[0], m1 = mp[1], m2 = mp[2], m3 = mp[3];
            m[0]=m0.x; m[1]=m0.y; m[2]=m0.z; m[3]=m0.w;
            m[4]=m1.x; m[5]=m1.y; m[6]=m1.z; m[7]=m1.w;
            m[8]=m2.x; m[9]=m2.y; m[10]=m2.z; m[11]=m2.w;
            m[12]=m3.x; m[13]=m3.y; m[14]=m3.z; m[15]=m3.w;
        }

        float* QKw = QK + (w * 16) * 76;          // warp-private 16-row slice

        #pragma unroll 1
        for (int hp = 0; hp < 4; hp++) {
            // ---- QKV GEMM for this head pair: 9 n-chunks (Q,K,V x 3) ----
            #pragma unroll 1
            for (int sj = 0; sj < 9; sj++) {
                int sec = sj / 3, j = sj % 3;
                int ncg = sec * 12 + hp * 3 + j;
                float2 bb = *(const float2*)&BQf[sec * 96 + hp * 24 + j * 8 + 2 * tg];
                float c0 = bb.x, c1 = bb.y, c2 = bb.x, c3 = bb.y;
                const u32* bp = PQ + ncg * 768 + ln * 2;
                #pragma unroll
                for (int ks = 0; ks < 12; ks++) {
                    uint2 bv = *(const uint2*)(bp + ks * 64);
                    mma8(c0, c1, c2, c3,
                         af[ks*4], af[ks*4+1], af[ks*4+2], af[ks*4+3],
                         bv.x, bv.y);
                }
                int qc = sec * 24 + j * 8 + 2 * tg;
                *(float2*)&QKw[gi * 76 + qc]       = make_float2(c0, c1);
                *(float2*)&QKw[(gi + 8) * 76 + qc] = make_float2(c2, c3);
            }
            __syncwarp();

            // ---- attention: lane = (hsel, ti), head h = 2hp+hsel ----
            {
                const int h = 2 * hp + hsel;
                const float4* qp = (const float4*)&QKw[ti * 76 + hsel * 12];
                float4 q0 = qp[0], q1 = qp[1], q2 = qp[2];
                float q[12] = { q0.x*SCALE, q0.y*SCALE, q0.z*SCALE, q0.w*SCALE,
                                q1.x*SCALE, q1.y*SCALE, q1.z*SCALE, q1.w*SCALE,
                                q2.x*SCALE, q2.y*SCALE, q2.z*SCALE, q2.w*SCALE };
                const float* kb = QKw + 24 + hsel * 12;
                const float* rb = RB + hp * 512 + ti * 2 + hsel;
                float sc[16];
                #pragma unroll
                for (int j = 0; j < 16; j++) {
                    const float4* kk = (const float4*)(kb + j * 76);
                    float4 k0 = kk[0], k1 = kk[1], k2 = kk[2];
                    float s = rb[j * 32] + m[j];
                    s += q[0]*k0.x + q[1]*k0.y + q[2] *k0.z + q[3] *k0.w
                       + q[4]*k1.x + q[5]*k1.y + q[6] *k1.z + q[7] *k1.w
                       + q[8]*k2.x + q[9]*k2.y + q[10]*k2.z + q[11]*k2.w;
                    sc[j] = s;
                }
                float mx = sc[0];
                #pragma unroll
                for (int j = 1; j < 16; j++) mx = fmaxf(mx, sc[j]);
                float sum = 0.f;
                #pragma unroll
                for (int j = 0; j < 16; j++) { sc[j] = __expf(sc[j] - mx); sum += sc[j]; }
                float inv = __fdividef(1.f, sum);

                float o[12];
                #pragma unroll
                for (int d = 0; d < 12; d++) o[d] = 0.f;
                const float* vb = QKw + 48 + hsel * 12;
                #pragma unroll
                for (int j = 0; j < 16; j++) {
                    const float4* vv = (const float4*)(vb + j * 76);
                    float4 v0 = vv[0], v1 = vv[1], v2 = vv[2];
                    float p = sc[j];
                    o[0] += p*v0.x; o[1] += p*v0.y; o[2]  += p*v0.z; o[3]  += p*v0.w;
                    o[4] += p*v1.x; o[5] += p*v1.y; o[6]  += p*v1.z; o[7]  += p*v1.w;
                    o[8] += p*v2.x; o[9] += p*v2.y; o[10] += p*v2.z; o[11] += p*v2.w;
                }
                float* op = OSf + (w * 16 + ti) * 100 + h * 12;
                ((float4*)op)[0] = make_float4(o[0]*inv, o[1]*inv, o[2]*inv, o[3]*inv);
                ((float4*)op)[1] = make_float4(o[4]*inv, o[5]*inv, o[6]*inv, o[7]*inv);
                ((float4*)op)[2] = make_float4(o[8]*inv, o[9]*inv, o[10]*inv, o[11]*inv);
            }
            __syncwarp();
        }

        // ---- proj GEMM: A from OSf, B from PRJPACK, D -> out ----
        {
            u32 pf[48];
            const float* ow = OSf + (w * 16 + gi) * 100 + tg;
            #pragma unroll
            for (int ks = 0; ks < 12; ks++) {
                pf[ks*4+0] = f2tf(ow[ks*8]);
                pf[ks*4+1] = f2tf(ow[800 + ks*8]);
                pf[ks*4+2] = f2tf(ow[ks*8 + 4]);
                pf[ks*4+3] = f2tf(ow[800 + ks*8 + 4]);
            }
            float* orow = out + ((size_t)g * 128 + w * 16 + gi) * 96 + 2 * tg;
            #pragma unroll 1
            for (int nc = 0; nc < 12; nc++) {
                float2 bb = *(const float2*)&BPf[nc * 8 + 2 * tg];
                float c0 = bb.x, c1 = bb.y, c2 = bb.x, c3 = bb.y;
                const u32* pp = PRJPACK + nc * 768 + ln * 2;
                #pragma unroll
                for (int ks = 0; ks < 12; ks++) {
                    uint2 bv = *(const uint2*)(pp + ks * 64);
                    mma8(c0, c1, c2, c3,
                         pf[ks*4], pf[ks*4+1], pf[ks*4+2], pf[ks*4+3],
                         bv.x, bv.y);
                }
                *(float2*)(orow + nc * 8)           = make_float2(c0, c1);
                *(float2*)(orow + nc * 8 + 8 * 96)  = make_float2(c2, c3);
            }
        }
        __syncwarp();   // protect OSf before next tile's attention writes
    }
}

extern "C" void kernel_launch(void* const* d_in, const int* in_sizes, int n_in,
                              void* d_out, int out_size)
{
    const float* x          = (const float*)d_in[0];
    const float* mask       = (const float*)d_in[1];
    const float* qkv_w      = (const float*)d_in[2];
    const float* qkv_b      = (const float*)d_in[3];
    const float* proj_w     = (const float*)d_in[4];
    const float* proj_b     = (const float*)d_in[5];
    const float* bias_table = (const float*)d_in[6];
    float* out = (float*)d_out;

    int sms = 148;
    cudaDeviceGetAttribute(&sms, cudaDevAttrMultiProcessorCount, 0);
    cudaFuncSetAttribute(win_attn_kernel,
                         cudaFuncAttributeMaxDynamicSharedMemorySize, SMEM_BYTES);

    win_attn_kernel<<<sms, 256, SMEM_BYTES>>>(x, mask, qkv_w, qkv_b,
                                              proj_w, proj_b, bias_table, out);
}